// round 5
// baseline (speedup 1.0000x reference)
#include <cuda_runtime.h>
#include <cstdint>

// ---------------------------------------------------------------------------
// SPELL forward, algebraically collapsed:
//   per node:  a[4] = feat128 . Wa + x4 . Sa + Ta[spk_idx] + Ca   (face cols 0,1; body cols 2,3)
//              b[4] = feat128 . Wb + x4 . Sb + Tb[spk_idx] + Cb
//   per edge:  m[dst] = max(m[dst], b[src])          (4 channels, ordered-uint atomicMax)
//   output:    out[i] = hasEdge ? (a_f + m_f) + (a_b + m_b) : 0
// ---------------------------------------------------------------------------

#define MAXN   50176
#define D_IN   901
#define INITU  0x007fffffu   // f2u(-inf)

__device__ float  g_Wa[512];   // [col][k]  col = fam*2 + c, k<128  (layout col*128+k)
__device__ float  g_Wb[512];
__device__ float  g_Sa[16];    // col*4 + t
__device__ float  g_Sb[16];
__device__ float  g_Ta[12];    // col*3 + r
__device__ float  g_Tb[12];
__device__ float  g_Ca[4];
__device__ float  g_Cb[4];
__device__ float4 g_a[MAXN];
__device__ float4 g_b[MAXN];
__device__ uint4  g_m[MAXN];

__device__ __forceinline__ unsigned f2u(float f) {
    unsigned u = __float_as_uint(f);
    return (u & 0x80000000u) ? ~u : (u | 0x80000000u);
}
__device__ __forceinline__ float u2f(unsigned u) {
    unsigned v = (u & 0x80000000u) ? (u & 0x7fffffffu) : ~u;
    return __uint_as_float(v);
}

// ---------------------------------------------------------------------------
// Precompute composed weights. 256 threads, each handles one (fam,k,c) of the
// main 128x2x2 composition; small side tables done by low threads.
// __launch_bounds__ pins the register budget so launch cannot fail.
// ---------------------------------------------------------------------------
__global__ void __launch_bounds__(256, 1) precompute_kernel(
    const float* __restrict__ spkw, const float* __restrict__ spkb,
    const float* __restrict__ spaw, const float* __restrict__ spab,
    const float* __restrict__ f1w,  const float* __restrict__ f1b,
    const float* __restrict__ f2w,  const float* __restrict__ f2b,
    const float* __restrict__ few,  const float* __restrict__ feb,
    const float* __restrict__ g1w,  const float* __restrict__ g1b,
    const float* __restrict__ g2w,  const float* __restrict__ g2b,
    const float* __restrict__ gew,  const float* __restrict__ geb)
{
    int tid = threadIdx.x;             // 256 threads

    // main composed weight: 2 fams x 128 k x 2 c  (two passes of 256)
    for (int fam = 0; fam < 2; fam++) {
        int k = tid >> 1, c = tid & 1;
        const float* w1 = fam ? g1w : f1w;
        const float* w2 = fam ? g2w : f2w;
        const float* we = fam ? gew : few;
        int col = fam * 2 + c;
        float sa = 0.f, sb = 0.f;
        for (int j = 0; j < 64; j++) {
            float web = we[(64 + j) * 2 + c];
            float wea = we[j * 2 + c] - web;
            float wk  = w1[k * 64 + j] + w2[k * 64 + j];
            sa += wk * wea;
            sb += wk * web;
        }
        g_Wa[col * 128 + k] = sa;
        g_Wb[col * 128 + k] = sb;
    }

    // spatial composition: Sa/Sb [col][t]  (16 entries)
    if (tid < 16) {
        int fam = tid >> 3, t = (tid >> 1) & 3, c = tid & 1;
        const float* w2 = fam ? g2w : f2w;
        const float* we = fam ? gew : few;
        float sA = 0.f, sB = 0.f;
        for (int s = 0; s < 16; s++) {
            float pa = 0.f, pb = 0.f;
            for (int j = 0; j < 64; j++) {
                float web = we[(64 + j) * 2 + c];
                float wea = we[j * 2 + c] - web;
                float v   = w2[(144 + s) * 64 + j];
                pa += v * wea;
                pb += v * web;
            }
            float sw = spaw[t * 16 + s];
            sA += sw * pa;
            sB += sw * pb;
        }
        int col = fam * 2 + c;
        g_Sa[col * 4 + t] = sA;
        g_Sb[col * 4 + t] = sB;
    }

    // speaker-count table: Ta/Tb [col][r]  (12 entries)
    if (tid >= 32 && tid < 44) {
        int t2 = tid - 32;
        int fam = t2 / 6, rr = (t2 >> 1) % 3, c = t2 & 1;
        const float* w2 = fam ? g2w : f2w;
        const float* we = fam ? gew : few;
        float sA = 0.f, sB = 0.f;
        for (int s = 0; s < 16; s++) {
            float pa = 0.f, pb = 0.f;
            for (int j = 0; j < 64; j++) {
                float web = we[(64 + j) * 2 + c];
                float wea = we[j * 2 + c] - web;
                float v   = w2[(128 + s) * 64 + j];
                pa += v * wea;
                pb += v * web;
            }
            float sw = spkw[rr * 16 + s] + spkb[s];
            sA += sw * pa;
            sB += sw * pb;
        }
        int col = fam * 2 + c;
        g_Ta[col * 3 + rr] = sA;
        g_Tb[col * 3 + rr] = sB;
    }

    // constant terms: Ca/Cb [col]  (4 entries)
    if (tid >= 64 && tid < 68) {
        int t2 = tid - 64;
        int fam = t2 >> 1, c = t2 & 1;
        const float* b1 = fam ? g1b : f1b;
        const float* b2 = fam ? g2b : f2b;
        const float* w2 = fam ? g2w : f2w;
        const float* we = fam ? gew : few;
        const float* eb = fam ? geb : feb;
        float cA = eb[c], cB = 0.f;
        for (int j = 0; j < 64; j++) {
            float web = we[(64 + j) * 2 + c];
            float wea = we[j * 2 + c] - web;
            float bj  = b1[j] + b2[j];
            cA += bj * wea;
            cB += bj * web;
        }
        for (int s = 0; s < 16; s++) {
            float pa = 0.f, pb = 0.f;
            for (int j = 0; j < 64; j++) {
                float web = we[(64 + j) * 2 + c];
                float wea = we[j * 2 + c] - web;
                float vv  = w2[(144 + s) * 64 + j];
                pa += vv * wea;
                pb += vv * web;
            }
            cA += spab[s] * pa;
            cB += spab[s] * pb;
        }
        int col = fam * 2 + c;
        g_Ca[col] = cA;
        g_Cb[col] = cB;
    }
}

// ---------------------------------------------------------------------------
// Node kernel: one warp per node; coalesced stride-32 reads of the 256 feature
// columns; 8-way warp reduction; lane 0 handles the 5-column tail + writes.
// ---------------------------------------------------------------------------
__global__ void __launch_bounds__(256) node_kernel(const float* __restrict__ x, int N)
{
    __shared__ float sWa[512];
    __shared__ float sWb[512];
    for (int i = threadIdx.x; i < 512; i += 256) {
        sWa[i] = g_Wa[i];
        sWb[i] = g_Wb[i];
    }
    __syncthreads();

    int warp = threadIdx.x >> 5;
    int lane = threadIdx.x & 31;
    int node = blockIdx.x * 8 + warp;
    if (node >= N) return;

    const float* row = x + (size_t)node * D_IN;

    float sA[4] = {0.f, 0.f, 0.f, 0.f};
    float sB[4] = {0.f, 0.f, 0.f, 0.f};
#pragma unroll
    for (int j = 0; j < 4; j++) {
        int k = lane + 32 * j;
        float vf = __ldg(row + k);
        float vb = __ldg(row + 128 + k);
        sA[0] += vf * sWa[k];
        sA[1] += vf * sWa[128 + k];
        sA[2] += vb * sWa[256 + k];
        sA[3] += vb * sWa[384 + k];
        sB[0] += vf * sWb[k];
        sB[1] += vf * sWb[128 + k];
        sB[2] += vb * sWb[256 + k];
        sB[3] += vb * sWb[384 + k];
    }
#pragma unroll
    for (int off = 16; off; off >>= 1) {
#pragma unroll
        for (int c = 0; c < 4; c++) {
            sA[c] += __shfl_xor_sync(0xffffffffu, sA[c], off);
            sB[c] += __shfl_xor_sync(0xffffffffu, sB[c], off);
        }
    }
    if (lane == 0) {
        float t0 = __ldg(row + 896);
        float t1 = __ldg(row + 897);
        float t2 = __ldg(row + 898);
        float t3 = __ldg(row + 899);
        float cnt = __ldg(row + 900);
        int idx = (int)cnt - 1;
        if (idx < 0) idx = 0;
        if (idx > 2) idx = 2;
        float av[4], bv[4];
#pragma unroll
        for (int c = 0; c < 4; c++) {
            av[c] = sA[c] + t0 * g_Sa[c * 4 + 0] + t1 * g_Sa[c * 4 + 1]
                          + t2 * g_Sa[c * 4 + 2] + t3 * g_Sa[c * 4 + 3]
                          + g_Ta[c * 3 + idx] + g_Ca[c];
            bv[c] = sB[c] + t0 * g_Sb[c * 4 + 0] + t1 * g_Sb[c * 4 + 1]
                          + t2 * g_Sb[c * 4 + 2] + t3 * g_Sb[c * 4 + 3]
                          + g_Tb[c * 3 + idx] + g_Cb[c];
        }
        g_a[node] = make_float4(av[0], av[1], av[2], av[3]);
        g_b[node] = make_float4(bv[0], bv[1], bv[2], bv[3]);
        g_m[node] = make_uint4(INITU, INITU, INITU, INITU);
    }
}

// ---------------------------------------------------------------------------
// Edge kernel: gather b[src] (L2-resident), RED.MAX into m[dst].
// ---------------------------------------------------------------------------
__global__ void __launch_bounds__(256) edge_kernel(
    const int* __restrict__ ei, const int* __restrict__ ea, int E)
{
    int e = blockIdx.x * blockDim.x + threadIdx.x;
    if (e >= E) return;
    int attr = ea[e];
    if (attr != 111 && attr != 0) return;
    int src = ei[e];
    int dst = ei[E + e];
    float4 bv = g_b[src];
    unsigned* m = (unsigned*)&g_m[dst];
    atomicMax(m + 0, f2u(bv.x));
    atomicMax(m + 1, f2u(bv.y));
    atomicMax(m + 2, f2u(bv.z));
    atomicMax(m + 3, f2u(bv.w));
}

// ---------------------------------------------------------------------------
// Output kernel: combine face+body; empty segments -> 0.
// ---------------------------------------------------------------------------
__global__ void __launch_bounds__(256) out_kernel(float* __restrict__ out, int N)
{
    int i = blockIdx.x * blockDim.x + threadIdx.x;
    if (i >= N) return;
    uint4 mu = g_m[i];
    float2 o;
    if (mu.x == INITU) {
        o.x = 0.f;
        o.y = 0.f;
    } else {
        float4 a = g_a[i];
        o.x = (a.x + u2f(mu.x)) + (a.z + u2f(mu.z));
        o.y = (a.y + u2f(mu.y)) + (a.w + u2f(mu.w));
    }
    ((float2*)out)[i] = o;
}

extern "C" void kernel_launch(void* const* d_in, const int* in_sizes, int n_in,
                              void* d_out, int out_size)
{
    const float* x    = (const float*)d_in[0];
    const int*   ei   = (const int*)d_in[1];
    const int*   ea   = (const int*)d_in[2];
    const float* spkw = (const float*)d_in[3];
    const float* spkb = (const float*)d_in[4];
    const float* spaw = (const float*)d_in[5];
    const float* spab = (const float*)d_in[6];
    const float* f1w  = (const float*)d_in[7];
    const float* f1b  = (const float*)d_in[8];
    const float* f2w  = (const float*)d_in[9];
    const float* f2b  = (const float*)d_in[10];
    const float* few  = (const float*)d_in[11];
    const float* feb  = (const float*)d_in[12];
    const float* g1w  = (const float*)d_in[13];
    const float* g1b  = (const float*)d_in[14];
    const float* g2w  = (const float*)d_in[15];
    const float* g2b  = (const float*)d_in[16];
    const float* gew  = (const float*)d_in[17];
    const float* geb  = (const float*)d_in[18];

    int N = in_sizes[0] / D_IN;
    int E = in_sizes[2];

    precompute_kernel<<<1, 256>>>(spkw, spkb, spaw, spab,
                                  f1w, f1b, f2w, f2b, few, feb,
                                  g1w, g1b, g2w, g2b, gew, geb);
    node_kernel<<<(N + 7) / 8, 256>>>(x, N);
    edge_kernel<<<(E + 255) / 256, 256>>>(ei, ea, E);
    out_kernel<<<(N + 255) / 256, 256>>>((float*)d_out, N);
}

// round 6
// speedup vs baseline: 1.4061x; 1.4061x over previous
#include <cuda_runtime.h>
#include <cstdint>

// ---------------------------------------------------------------------------
// SPELL forward, algebraically collapsed:
//   per node:  a[4] = feat128 . Wa + x4 . Sa + Ta[spk_idx] + Ca   (face cols 0,1; body cols 2,3)
//              b[4] = feat128 . Wb + x4 . Sb + Tb[spk_idx] + Cb
//   per edge:  m[dst] = max(m[dst], b[src])          (4 channels, ordered-uint atomicMax)
//   output:    out[i] = hasEdge ? (a_f + m_f) + (a_b + m_b) : 0
// ---------------------------------------------------------------------------

#define MAXN   50176
#define D_IN   901
#define INITU  0x007fffffu   // f2u(-inf)

__device__ float  g_Wa[512];   // [col][k]  col = fam*2 + c, k<128  (layout col*128+k)
__device__ float  g_Wb[512];
__device__ float  g_Sa[16];    // col*4 + t
__device__ float  g_Sb[16];
__device__ float  g_Ta[12];    // col*3 + r
__device__ float  g_Tb[12];
__device__ float  g_Ca[4];
__device__ float  g_Cb[4];
__device__ float4 g_a[MAXN];
__device__ float4 g_b[MAXN];
__device__ uint4  g_m[MAXN];

__device__ __forceinline__ unsigned f2u(float f) {
    unsigned u = __float_as_uint(f);
    return (u & 0x80000000u) ? ~u : (u | 0x80000000u);
}
__device__ __forceinline__ float u2f(unsigned u) {
    unsigned v = (u & 0x80000000u) ? (u & 0x7fffffffu) : ~u;
    return __uint_as_float(v);
}

// ---------------------------------------------------------------------------
// Precompute composed weights. grid=2 (blockIdx.x = fam), 256 threads.
// All reductions are <=64 serial iterations, run by many threads in parallel;
// side tables factored through P[s][c] intermediates staged in shared memory.
// ---------------------------------------------------------------------------
__global__ void __launch_bounds__(256, 1) precompute_kernel(
    const float* __restrict__ spkw, const float* __restrict__ spkb,
    const float* __restrict__ spaw, const float* __restrict__ spab,
    const float* __restrict__ f1w,  const float* __restrict__ f1b,
    const float* __restrict__ f2w,  const float* __restrict__ f2b,
    const float* __restrict__ few,  const float* __restrict__ feb,
    const float* __restrict__ g1w,  const float* __restrict__ g1b,
    const float* __restrict__ g2w,  const float* __restrict__ g2b,
    const float* __restrict__ gew,  const float* __restrict__ geb)
{
    int fam = blockIdx.x;
    int tid = threadIdx.x;
    const float* w1 = fam ? g1w : f1w;
    const float* b1 = fam ? g1b : f1b;
    const float* w2 = fam ? g2w : f2w;
    const float* b2 = fam ? g2b : f2b;
    const float* we = fam ? gew : few;
    const float* eb = fam ? geb : feb;

    __shared__ float s_wea[2][64], s_web[2][64];       // [c][j]
    __shared__ float s_Pa[2][2][16], s_Pb[2][2][16];   // [which][c][s]  which: 0=spk 1=spa

    if (tid < 128) {
        int j = tid >> 1, c = tid & 1;
        float wb = we[(64 + j) * 2 + c];
        s_web[c][j] = wb;
        s_wea[c][j] = we[j * 2 + c] - wb;
    }
    __syncthreads();

    // main composed weight: (k,c) per thread, 64-iter j loop
    {
        int k = tid >> 1, c = tid & 1;
        float sa = 0.f, sb = 0.f;
        for (int j = 0; j < 64; j++) {
            float wk = w1[k * 64 + j] + w2[k * 64 + j];
            sa += wk * s_wea[c][j];
            sb += wk * s_web[c][j];
        }
        int col = fam * 2 + c;
        g_Wa[col * 128 + k] = sa;
        g_Wb[col * 128 + k] = sb;
    }

    // P intermediates: 64 tasks (which, c, s), 64-iter j loop each
    if (tid < 64) {
        int which = tid & 1, c = (tid >> 1) & 1, s = tid >> 2;
        int row = which ? (144 + s) : (128 + s);
        float pa = 0.f, pb = 0.f;
        for (int j = 0; j < 64; j++) {
            float v = w2[row * 64 + j];
            pa += v * s_wea[c][j];
            pb += v * s_web[c][j];
        }
        s_Pa[which][c][s] = pa;
        s_Pb[which][c][s] = pb;
    }
    __syncthreads();

    // spatial table Sa/Sb [col][t]: 8 tasks, 16-iter loop
    if (tid < 8) {
        int t = tid >> 1, c = tid & 1;
        float sA = 0.f, sB = 0.f;
        for (int s = 0; s < 16; s++) {
            float sw = spaw[t * 16 + s];
            sA += sw * s_Pa[1][c][s];
            sB += sw * s_Pb[1][c][s];
        }
        int col = fam * 2 + c;
        g_Sa[col * 4 + t] = sA;
        g_Sb[col * 4 + t] = sB;
    }

    // speaker table Ta/Tb [col][r]: 6 tasks, 16-iter loop
    if (tid >= 32 && tid < 38) {
        int t2 = tid - 32;
        int rr = t2 >> 1, c = t2 & 1;
        float sA = 0.f, sB = 0.f;
        for (int s = 0; s < 16; s++) {
            float sw = spkw[rr * 16 + s] + spkb[s];
            sA += sw * s_Pa[0][c][s];
            sB += sw * s_Pb[0][c][s];
        }
        int col = fam * 2 + c;
        g_Ta[col * 3 + rr] = sA;
        g_Tb[col * 3 + rr] = sB;
    }

    // constant terms Ca/Cb [col]: 2 tasks, 64+16 iters
    if (tid >= 64 && tid < 66) {
        int c = tid - 64;
        float cA = eb[c], cB = 0.f;
        for (int j = 0; j < 64; j++) {
            float bj = b1[j] + b2[j];
            cA += bj * s_wea[c][j];
            cB += bj * s_web[c][j];
        }
        for (int s = 0; s < 16; s++) {
            float sb = spab[s];
            cA += sb * s_Pa[1][c][s];
            cB += sb * s_Pb[1][c][s];
        }
        int col = fam * 2 + c;
        g_Ca[col] = cA;
        g_Cb[col] = cB;
    }
}

// ---------------------------------------------------------------------------
// Node kernel: one warp per node; coalesced stride-32 reads of the 256 feature
// columns; 8-way warp reduction; lanes 0-4 read the 5-column tail.
// ---------------------------------------------------------------------------
__global__ void __launch_bounds__(256) node_kernel(const float* __restrict__ x, int N)
{
    __shared__ float sWa[512];
    __shared__ float sWb[512];
    for (int i = threadIdx.x; i < 512; i += 256) {
        sWa[i] = g_Wa[i];
        sWb[i] = g_Wb[i];
    }
    __syncthreads();

    int warp = threadIdx.x >> 5;
    int lane = threadIdx.x & 31;
    int node = blockIdx.x * 8 + warp;
    if (node >= N) return;

    const float* row = x + (size_t)node * D_IN;

    // tail columns (896..900) read by lanes 0..4 in parallel, broadcast later
    float tailv = (lane < 5) ? __ldg(row + 896 + lane) : 0.f;

    float sA[4] = {0.f, 0.f, 0.f, 0.f};
    float sB[4] = {0.f, 0.f, 0.f, 0.f};
#pragma unroll
    for (int j = 0; j < 4; j++) {
        int k = lane + 32 * j;
        float vf = __ldg(row + k);
        float vb = __ldg(row + 128 + k);
        sA[0] += vf * sWa[k];
        sA[1] += vf * sWa[128 + k];
        sA[2] += vb * sWa[256 + k];
        sA[3] += vb * sWa[384 + k];
        sB[0] += vf * sWb[k];
        sB[1] += vf * sWb[128 + k];
        sB[2] += vb * sWb[256 + k];
        sB[3] += vb * sWb[384 + k];
    }
#pragma unroll
    for (int off = 16; off; off >>= 1) {
#pragma unroll
        for (int c = 0; c < 4; c++) {
            sA[c] += __shfl_xor_sync(0xffffffffu, sA[c], off);
            sB[c] += __shfl_xor_sync(0xffffffffu, sB[c], off);
        }
    }
    float t0  = __shfl_sync(0xffffffffu, tailv, 0);
    float t1  = __shfl_sync(0xffffffffu, tailv, 1);
    float t2  = __shfl_sync(0xffffffffu, tailv, 2);
    float t3  = __shfl_sync(0xffffffffu, tailv, 3);
    float cnt = __shfl_sync(0xffffffffu, tailv, 4);
    if (lane == 0) {
        int idx = (int)cnt - 1;
        if (idx < 0) idx = 0;
        if (idx > 2) idx = 2;
        float av[4], bv[4];
#pragma unroll
        for (int c = 0; c < 4; c++) {
            av[c] = sA[c] + t0 * g_Sa[c * 4 + 0] + t1 * g_Sa[c * 4 + 1]
                          + t2 * g_Sa[c * 4 + 2] + t3 * g_Sa[c * 4 + 3]
                          + g_Ta[c * 3 + idx] + g_Ca[c];
            bv[c] = sB[c] + t0 * g_Sb[c * 4 + 0] + t1 * g_Sb[c * 4 + 1]
                          + t2 * g_Sb[c * 4 + 2] + t3 * g_Sb[c * 4 + 3]
                          + g_Tb[c * 3 + idx] + g_Cb[c];
        }
        g_a[node] = make_float4(av[0], av[1], av[2], av[3]);
        g_b[node] = make_float4(bv[0], bv[1], bv[2], bv[3]);
        g_m[node] = make_uint4(INITU, INITU, INITU, INITU);
    }
}

// ---------------------------------------------------------------------------
// Edge kernel: gather b[src] (L2-resident); read-before-atomic filter, then
// RED.MAX into m[dst] only when this edge can raise the max.
// ---------------------------------------------------------------------------
__global__ void __launch_bounds__(256) edge_kernel(
    const int* __restrict__ ei, const int* __restrict__ ea, int E)
{
    int e = blockIdx.x * blockDim.x + threadIdx.x;
    if (e >= E) return;
    int attr = ea[e];
    if (attr != 111 && attr != 0) return;
    int src = ei[e];
    int dst = ei[E + e];
    float4 bv = g_b[src];
    unsigned u0 = f2u(bv.x), u1 = f2u(bv.y), u2 = f2u(bv.z), u3 = f2u(bv.w);
    uint4 cur = *(const uint4*)&g_m[dst];   // non-atomic peek (monotone, safe)
    unsigned* m = (unsigned*)&g_m[dst];
    if (u0 > cur.x) atomicMax(m + 0, u0);
    if (u1 > cur.y) atomicMax(m + 1, u1);
    if (u2 > cur.z) atomicMax(m + 2, u2);
    if (u3 > cur.w) atomicMax(m + 3, u3);
}

// ---------------------------------------------------------------------------
// Output kernel: combine face+body; empty segments -> 0.
// ---------------------------------------------------------------------------
__global__ void __launch_bounds__(256) out_kernel(float* __restrict__ out, int N)
{
    int i = blockIdx.x * blockDim.x + threadIdx.x;
    if (i >= N) return;
    uint4 mu = g_m[i];
    float2 o;
    if (mu.x == INITU) {
        o.x = 0.f;
        o.y = 0.f;
    } else {
        float4 a = g_a[i];
        o.x = (a.x + u2f(mu.x)) + (a.z + u2f(mu.z));
        o.y = (a.y + u2f(mu.y)) + (a.w + u2f(mu.w));
    }
    ((float2*)out)[i] = o;
}

extern "C" void kernel_launch(void* const* d_in, const int* in_sizes, int n_in,
                              void* d_out, int out_size)
{
    const float* x    = (const float*)d_in[0];
    const int*   ei   = (const int*)d_in[1];
    const int*   ea   = (const int*)d_in[2];
    const float* spkw = (const float*)d_in[3];
    const float* spkb = (const float*)d_in[4];
    const float* spaw = (const float*)d_in[5];
    const float* spab = (const float*)d_in[6];
    const float* f1w  = (const float*)d_in[7];
    const float* f1b  = (const float*)d_in[8];
    const float* f2w  = (const float*)d_in[9];
    const float* f2b  = (const float*)d_in[10];
    const float* few  = (const float*)d_in[11];
    const float* feb  = (const float*)d_in[12];
    const float* g1w  = (const float*)d_in[13];
    const float* g1b  = (const float*)d_in[14];
    const float* g2w  = (const float*)d_in[15];
    const float* g2b  = (const float*)d_in[16];
    const float* gew  = (const float*)d_in[17];
    const float* geb  = (const float*)d_in[18];

    int N = in_sizes[0] / D_IN;
    int E = in_sizes[2];

    precompute_kernel<<<2, 256>>>(spkw, spkb, spaw, spab,
                                  f1w, f1b, f2w, f2b, few, feb,
                                  g1w, g1b, g2w, g2b, gew, geb);
    node_kernel<<<(N + 7) / 8, 256>>>(x, N);
    edge_kernel<<<(E + 255) / 256, 256>>>(ei, ea, E);
    out_kernel<<<(N + 255) / 256, 256>>>((float*)d_out, N);
}